// round 3
// baseline (speedup 1.0000x reference)
#include <cuda_runtime.h>
#include <cuda_fp16.h>

// Problem constants (fixed by the dataset)
#define NN   50000
#define EE   800000
#define ETOT (NN + EE)      // edges + self loops
#define D1   128            // DIN and H*C1
#define HH   4
#define CC1  32
#define DOUT 32
#define SLOPE 0.2f
#define NCH  ((NN + 1023) / 1024)   // 49 scan chunks

// ---------------- scratch (static device arrays: no allocation) -------------
__device__ int     g_deg[NN];
__device__ int     g_off[NN + 1];
__device__ int     g_cur[NN];
__device__ int     g_part[NCH];
__device__ int     g_flag[NCH];
__device__ int     g_ssrc[ETOT];
__device__ __half2 g_xp1h[NN * 64];   // xp1 in fp16, 2 ch per half2
__device__ float   g_h[NN * D1];
__device__ __half  g_xp2h[NN * DOUT]; // xp2 in fp16
__device__ float   g_as1[NN * HH];
__device__ float   g_ad1[NN * HH];
__device__ float   g_as2[NN];
__device__ float   g_ad2[NN];

__device__ __forceinline__ float leaky(float v) { return v > 0.f ? v : SLOPE * v; }

// packed fp32x2 FMA (Blackwell): d = a*b + d on two lanes at once
__device__ __forceinline__ void fma2(unsigned long long& d, unsigned long long a,
                                     unsigned long long b) {
    asm("fma.rn.f32x2 %0, %1, %2, %0;" : "+l"(d) : "l"(a), "l"(b));
}
__device__ __forceinline__ unsigned long long pack2(float x) {
    unsigned long long r;
    asm("mov.b64 %0, {%1, %1};" : "=l"(r) : "f"(x));
    return r;
}
__device__ __forceinline__ float2 unpk2(unsigned long long v) {
    float2 r;
    asm("mov.b64 {%0, %1}, %2;" : "=f"(r.x), "=f"(r.y) : "l"(v));
    return r;
}

// ---------------- CSR build -------------------------------------------------
__global__ void k_init() {
    int i = blockIdx.x * blockDim.x + threadIdx.x;
    if (i < NN) g_deg[i] = 1;   // self loop
    if (i < NCH) g_flag[i] = 0;
}

__global__ void k_degree(const int* __restrict__ dst) {
    int e4 = blockIdx.x * blockDim.x + threadIdx.x;
    if (e4 < EE / 4) {
        int4 d = ((const int4*)dst)[e4];
        atomicAdd(&g_deg[d.x], 1);
        atomicAdd(&g_deg[d.y], 1);
        atomicAdd(&g_deg[d.z], 1);
        atomicAdd(&g_deg[d.w], 1);
    }
}

// single-pass scan with lookback (49 blocks, all co-resident) + self loops
__global__ void __launch_bounds__(1024) k_scan() {
    __shared__ int s[1024];
    __shared__ int sbase;
    int t = threadIdx.x, b = blockIdx.x;
    int i = b * 1024 + t;
    int v = (i < NN) ? g_deg[i] : 0;
    s[t] = v;
    __syncthreads();
    #pragma unroll
    for (int d = 1; d < 1024; d <<= 1) {
        int x = (t >= d) ? s[t - d] : 0;
        __syncthreads();
        s[t] += x;
        __syncthreads();
    }
    if (t == 1023) {
        g_part[b] = s[1023];
        __threadfence();
        atomicExch(&g_flag[b], 1);
    }
    if (t == 0) {
        int acc = 0;
        for (int p = 0; p < b; p++) {
            while (atomicAdd(&g_flag[p], 0) == 0) { }
            acc += g_part[p];
        }
        sbase = acc;
    }
    __syncthreads();
    if (i < NN) {
        int o = sbase + s[t] - v;    // exclusive prefix
        g_off[i] = o;
        g_cur[i] = 1;                // slot 0 of each segment = self loop
        g_ssrc[o] = i;
    }
    if (i == 0) g_off[NN] = ETOT;
}

__global__ void k_scatter(const int* __restrict__ ei) {
    int e4 = blockIdx.x * blockDim.x + threadIdx.x;
    if (e4 < EE / 4) {
        int4 s = ((const int4*)ei)[e4];
        int4 d = ((const int4*)(ei + EE))[e4];
        int p;
        p = g_off[d.x] + atomicAdd(&g_cur[d.x], 1); g_ssrc[p] = s.x;
        p = g_off[d.y] + atomicAdd(&g_cur[d.y], 1); g_ssrc[p] = s.y;
        p = g_off[d.z] + atomicAdd(&g_cur[d.z], 1); g_ssrc[p] = s.z;
        p = g_off[d.w] + atomicAdd(&g_cur[d.w], 1); g_ssrc[p] = s.w;
    }
}

// ---- GEMM1: xp1 = x @ W1 (50000x128 @ 128x128) + fused attention dots ------
// block: 64 rows x 128 cols, 256 threads; warp = 8 rows (uniform) x 128 cols;
// thread = 8 rows x 4 cols, accumulated as fp32x2 pairs.  xp1 stored fp16.
__global__ void __launch_bounds__(256)
k_gemm1(const float* __restrict__ x, const float* __restrict__ W,
        const float* __restrict__ asrc, const float* __restrict__ adst) {
    __shared__ float Ws[32][128];   // k-major
    __shared__ float Xs[32][64];    // k-major (transposed on load)
    int t = threadIdx.x;
    int lane = t & 31;
    int warp = t >> 5;
    int row0 = blockIdx.x * 64;
    int c0 = lane * 4;
    int r0 = warp * 8;

    unsigned long long acc[8][2];
    #pragma unroll
    for (int r = 0; r < 8; r++) { acc[r][0] = 0ull; acc[r][1] = 0ull; }

    for (int kc = 0; kc < 128; kc += 32) {
        #pragma unroll
        for (int i = 0; i < 4; i++) {
            int idx = t + i * 256;
            ((float4*)&Ws[0][0])[idx] = ((const float4*)(W + kc * 128))[idx];
        }
        #pragma unroll
        for (int i = 0; i < 2; i++) {
            int id = t + i * 256;          // 512 float4 = 64 rows x 32 k
            int row = id >> 3;
            int k4 = (id & 7) * 4;
            int grow = row0 + row;
            float4 v = (grow < NN) ? *(const float4*)(x + grow * 128 + kc + k4)
                                   : make_float4(0, 0, 0, 0);
            Xs[k4 + 0][row] = v.x; Xs[k4 + 1][row] = v.y;
            Xs[k4 + 2][row] = v.z; Xs[k4 + 3][row] = v.w;
        }
        __syncthreads();
        #pragma unroll 8
        for (int k = 0; k < 32; k++) {
            float4 alo = *(const float4*)&Xs[k][r0];       // warp-uniform rows
            float4 ahi = *(const float4*)&Xs[k][r0 + 4];
            ulonglong2 b = *(const ulonglong2*)&Ws[k][c0];
            unsigned long long ap;
            ap = pack2(alo.x); fma2(acc[0][0], ap, b.x); fma2(acc[0][1], ap, b.y);
            ap = pack2(alo.y); fma2(acc[1][0], ap, b.x); fma2(acc[1][1], ap, b.y);
            ap = pack2(alo.z); fma2(acc[2][0], ap, b.x); fma2(acc[2][1], ap, b.y);
            ap = pack2(alo.w); fma2(acc[3][0], ap, b.x); fma2(acc[3][1], ap, b.y);
            ap = pack2(ahi.x); fma2(acc[4][0], ap, b.x); fma2(acc[4][1], ap, b.y);
            ap = pack2(ahi.y); fma2(acc[5][0], ap, b.x); fma2(acc[5][1], ap, b.y);
            ap = pack2(ahi.z); fma2(acc[6][0], ap, b.x); fma2(acc[6][1], ap, b.y);
            ap = pack2(ahi.w); fma2(acc[7][0], ap, b.x); fma2(acc[7][1], ap, b.y);
        }
        __syncthreads();
    }

    // epilogue: store xp1 (fp16) + fused per-head attention dots (fp32)
    float4 asv = *(const float4*)(asrc + c0);
    float4 adv = *(const float4*)(adst + c0);
    int h = lane >> 3;
    #pragma unroll
    for (int r = 0; r < 8; r++) {
        float2 lo = unpk2(acc[r][0]);
        float2 hi = unpk2(acc[r][1]);
        int grow = row0 + r0 + r;
        if (grow < NN) {
            __half2 h0 = __floats2half2_rn(lo.x, lo.y);
            __half2 h1 = __floats2half2_rn(hi.x, hi.y);
            uint2 pk;
            pk.x = *(unsigned*)&h0;
            pk.y = *(unsigned*)&h1;
            *(uint2*)(g_xp1h + grow * 64 + lane * 2) = pk;
        }
        float ps = lo.x * asv.x + lo.y * asv.y + hi.x * asv.z + hi.y * asv.w;
        float pd = lo.x * adv.x + lo.y * adv.y + hi.x * adv.z + hi.y * adv.w;
        #pragma unroll
        for (int o = 1; o < 8; o <<= 1) {
            ps += __shfl_xor_sync(0xffffffffu, ps, o);
            pd += __shfl_xor_sync(0xffffffffu, pd, o);
        }
        if ((lane & 7) == 0 && grow < NN) {
            g_as1[grow * 4 + h] = ps;
            g_ad1[grow * 4 + h] = pd;
        }
    }
}

// ---- layer-1 aggregation: warp per node, fp16 gather, no max pass ----------
__global__ void __launch_bounds__(256) k_agg1(const float* __restrict__ b1) {
    int gw = (blockIdx.x * blockDim.x + threadIdx.x) >> 5;
    int lane = threadIdx.x & 31;
    if (gw >= NN) return;
    int i = gw;
    int s0 = g_off[i], s1 = g_off[i + 1];
    int h = lane >> 3;
    int es = lane & 7;
    float adh = g_ad1[i * 4 + h];

    float den = 0.f;
    float ax = 0.f, ay = 0.f, az = 0.f, aw = 0.f;
    int base = s0;
    for (; base + 8 <= s1; base += 8) {
        int src_l = g_ssrc[base + es];
        float w_l = __expf(leaky(g_as1[src_l * 4 + h] + adh));
        den += w_l;
        #pragma unroll 8
        for (int j = 0; j < 8; j++) {
            int sl = (h << 3) | j;
            int src = __shfl_sync(0xffffffffu, src_l, sl);
            float w  = __shfl_sync(0xffffffffu, w_l, sl);
            uint2 p = *(const uint2*)(g_xp1h + src * 64 + lane * 2);
            float2 v0 = __half22float2(*(__half2*)&p.x);
            float2 v1 = __half22float2(*(__half2*)&p.y);
            ax = fmaf(w, v0.x, ax); ay = fmaf(w, v0.y, ay);
            az = fmaf(w, v1.x, az); aw = fmaf(w, v1.y, aw);
        }
    }
    if (base < s1) {
        int e = base + es;
        int src_l = 0;
        float w_l = 0.f;
        if (e < s1) {
            src_l = g_ssrc[e];
            w_l = __expf(leaky(g_as1[src_l * 4 + h] + adh));
        }
        den += w_l;
        int n = s1 - base;
        for (int j = 0; j < n; j++) {
            int sl = (h << 3) | j;
            int src = __shfl_sync(0xffffffffu, src_l, sl);
            float w  = __shfl_sync(0xffffffffu, w_l, sl);
            uint2 p = *(const uint2*)(g_xp1h + src * 64 + lane * 2);
            float2 v0 = __half22float2(*(__half2*)&p.x);
            float2 v1 = __half22float2(*(__half2*)&p.y);
            ax = fmaf(w, v0.x, ax); ay = fmaf(w, v0.y, ay);
            az = fmaf(w, v1.x, az); aw = fmaf(w, v1.y, aw);
        }
    }
    den += __shfl_xor_sync(0xffffffffu, den, 1);
    den += __shfl_xor_sync(0xffffffffu, den, 2);
    den += __shfl_xor_sync(0xffffffffu, den, 4);
    float inv = 1.0f / den;
    float4 bb = *(const float4*)(b1 + lane * 4);
    float4 o;
    o.x = fmaxf(fmaf(ax, inv, bb.x), 0.f);
    o.y = fmaxf(fmaf(ay, inv, bb.y), 0.f);
    o.z = fmaxf(fmaf(az, inv, bb.z), 0.f);
    o.w = fmaxf(fmaf(aw, inv, bb.w), 0.f);
    *(float4*)(g_h + i * 128 + lane * 4) = o;
}

// ---- GEMM2: xp2 = h @ W2 (50000x128 @ 128x32) + fused attention dots -------
// block: 128 rows x 32 cols, 256 threads; thread = 8 rows x 2 cols (1 pair)
__global__ void __launch_bounds__(256)
k_gemm2(const float* __restrict__ W2,
        const float* __restrict__ asrc, const float* __restrict__ adst) {
    __shared__ float Ws[32][32];    // k-major
    __shared__ float Xs[32][128];   // k-major
    int t = threadIdx.x;
    int lane = t & 31;
    int row0 = blockIdx.x * 128;
    int c0 = (t & 15) * 2;
    int r0 = (t >> 4) * 8;

    unsigned long long acc[8];
    #pragma unroll
    for (int r = 0; r < 8; r++) acc[r] = 0ull;

    for (int kc = 0; kc < 128; kc += 32) {
        ((float4*)&Ws[0][0])[t] = ((const float4*)(W2 + kc * 32))[t];
        #pragma unroll
        for (int i = 0; i < 4; i++) {
            int id = t + i * 256;          // 1024 float4 = 128 rows x 32 k
            int row = id >> 3;
            int k4 = (id & 7) * 4;
            int grow = row0 + row;
            float4 v = (grow < NN) ? *(const float4*)(g_h + grow * 128 + kc + k4)
                                   : make_float4(0, 0, 0, 0);
            Xs[k4 + 0][row] = v.x; Xs[k4 + 1][row] = v.y;
            Xs[k4 + 2][row] = v.z; Xs[k4 + 3][row] = v.w;
        }
        __syncthreads();
        #pragma unroll 8
        for (int k = 0; k < 32; k++) {
            float4 alo = *(const float4*)&Xs[k][r0];
            float4 ahi = *(const float4*)&Xs[k][r0 + 4];
            unsigned long long b = *(const unsigned long long*)&Ws[k][c0];
            unsigned long long ap;
            ap = pack2(alo.x); fma2(acc[0], ap, b);
            ap = pack2(alo.y); fma2(acc[1], ap, b);
            ap = pack2(alo.z); fma2(acc[2], ap, b);
            ap = pack2(alo.w); fma2(acc[3], ap, b);
            ap = pack2(ahi.x); fma2(acc[4], ap, b);
            ap = pack2(ahi.y); fma2(acc[5], ap, b);
            ap = pack2(ahi.z); fma2(acc[6], ap, b);
            ap = pack2(ahi.w); fma2(acc[7], ap, b);
        }
        __syncthreads();
    }

    float2 asv = *(const float2*)(asrc + c0);
    float2 adv = *(const float2*)(adst + c0);
    #pragma unroll
    for (int r = 0; r < 8; r++) {
        float2 v = unpk2(acc[r]);
        int grow = row0 + r0 + r;
        if (grow < NN) {
            __half2 hv = __floats2half2_rn(v.x, v.y);
            *(__half2*)(g_xp2h + grow * 32 + c0) = hv;
        }
        float ps = v.x * asv.x + v.y * asv.y;
        float pd = v.x * adv.x + v.y * adv.y;
        #pragma unroll
        for (int o = 1; o < 16; o <<= 1) {
            ps += __shfl_xor_sync(0xffffffffu, ps, o);
            pd += __shfl_xor_sync(0xffffffffu, pd, o);
        }
        if ((lane & 15) == 0 && grow < NN) {
            g_as2[grow] = ps;
            g_ad2[grow] = pd;
        }
    }
}

// ---- layer-2 aggregation: warp per node, fp16 gather, no max pass ----------
__global__ void __launch_bounds__(256)
k_agg2(const float* __restrict__ b2, float* __restrict__ out) {
    int gw = (blockIdx.x * blockDim.x + threadIdx.x) >> 5;
    int lane = threadIdx.x & 31;
    if (gw >= NN) return;
    int i = gw;
    int s0 = g_off[i], s1 = g_off[i + 1];
    float ad = g_ad2[i];

    float den = 0.f, acc = 0.f;
    for (int base = s0; base < s1; base += 32) {
        int e = base + lane;
        int src_l = 0;
        float w_l = 0.f;
        if (e < s1) {
            src_l = g_ssrc[e];
            w_l = __expf(leaky(g_as2[src_l] + ad));
        }
        den += w_l;
        int n = min(32, s1 - base);
        #pragma unroll 4
        for (int j = 0; j < n; j++) {
            int src = __shfl_sync(0xffffffffu, src_l, j);
            float w  = __shfl_sync(0xffffffffu, w_l, j);
            float v = __half2float(g_xp2h[src * 32 + lane]);
            acc = fmaf(w, v, acc);
        }
    }
    #pragma unroll
    for (int o = 16; o; o >>= 1)
        den += __shfl_xor_sync(0xffffffffu, den, o);
    out[i * 32 + lane] = acc / den + b2[lane];
}

// ---------------- launch ----------------------------------------------------
extern "C" void kernel_launch(void* const* d_in, const int* in_sizes, int n_in,
                              void* d_out, int out_size) {
    const float* x   = (const float*)d_in[0];
    const int*   ei  = (const int*)  d_in[1];
    const float* W1  = (const float*)d_in[2];
    const float* as1 = (const float*)d_in[3];
    const float* ad1 = (const float*)d_in[4];
    const float* b1  = (const float*)d_in[5];
    const float* W2  = (const float*)d_in[6];
    const float* as2 = (const float*)d_in[7];
    const float* ad2 = (const float*)d_in[8];
    const float* b2  = (const float*)d_in[9];
    float* out = (float*)d_out;

    const int nblkN = (NN + 255) / 256;
    const int nblkE4 = (EE / 4 + 255) / 256;
    const int nblkW = (NN * 32 + 255) / 256;   // one warp per node

    // CSR build (4 launches)
    k_init<<<nblkN, 256>>>();
    k_degree<<<nblkE4, 256>>>(ei + EE);
    k_scan<<<NCH, 1024>>>();
    k_scatter<<<nblkE4, 256>>>(ei);

    // layer 1
    k_gemm1<<<(NN + 63) / 64, 256>>>(x, W1, as1, ad1);
    k_agg1<<<nblkW, 256>>>(b1);

    // layer 2
    k_gemm2<<<(NN + 127) / 128, 256>>>(W2, as2, ad2);
    k_agg2<<<nblkW, 256>>>(b2, out);
}

// round 4
// speedup vs baseline: 1.4130x; 1.4130x over previous
#include <cuda_runtime.h>
#include <cuda_fp16.h>
#include <mma.h>

using namespace nvcuda;

// Problem constants (fixed by the dataset)
#define NN   50000
#define EE   800000
#define ETOT (NN + EE)      // edges + self loops
#define D1   128            // DIN and H*C1
#define HH   4
#define CC1  32
#define DOUT 32
#define SLOPE 0.2f

// ---------------- scratch (static device arrays: no allocation) -------------
__device__ int     g_deg[NN];
__device__ int     g_off[NN + 1];
__device__ int     g_rank[EE];
__device__ int     g_part[64];
__device__ int     g_ssrc[ETOT];
__device__ __half2 g_xp1h[NN * 64];   // xp1 in fp16, 2 ch per half2
__device__ float   g_h[NN * D1];
__device__ __half  g_xp2h[NN * DOUT]; // xp2 in fp16
__device__ float   g_as1[NN * HH];
__device__ float   g_ad1[NN * HH];
__device__ float   g_as2[NN];
__device__ float   g_ad2[NN];

__device__ __forceinline__ float leaky(float v) { return v > 0.f ? v : SLOPE * v; }

// packed fp32x2 FMA (Blackwell)
__device__ __forceinline__ void fma2(unsigned long long& d, unsigned long long a,
                                     unsigned long long b) {
    asm("fma.rn.f32x2 %0, %1, %2, %0;" : "+l"(d) : "l"(a), "l"(b));
}
__device__ __forceinline__ unsigned long long pack2(float x) {
    unsigned long long r;
    asm("mov.b64 %0, {%1, %1};" : "=l"(r) : "f"(x));
    return r;
}
__device__ __forceinline__ float2 unpk2(unsigned long long v) {
    float2 r;
    asm("mov.b64 {%0, %1}, %2;" : "=f"(r.x), "=f"(r.y) : "l"(v));
    return r;
}

// ---------------- CSR build -------------------------------------------------
__global__ void k_init() {
    int i = blockIdx.x * blockDim.x + threadIdx.x;
    if (i < NN) g_deg[i] = 1;   // self loop
}

// degree count + per-edge rank in one pass (rank starts at 1; slot 0 = self)
__global__ void k_rank(const int* __restrict__ dst) {
    int e4 = blockIdx.x * blockDim.x + threadIdx.x;
    if (e4 < EE / 4) {
        int4 d = ((const int4*)dst)[e4];
        int4 r;
        r.x = atomicAdd(&g_deg[d.x], 1);
        r.y = atomicAdd(&g_deg[d.y], 1);
        r.z = atomicAdd(&g_deg[d.z], 1);
        r.w = atomicAdd(&g_deg[d.w], 1);
        ((int4*)g_rank)[e4] = r;
    }
}

__global__ void k_scan1() {   // grid = ceil(NN/1024), block 1024
    __shared__ int s[1024];
    int t = threadIdx.x;
    int i = blockIdx.x * 1024 + t;
    int v = (i < NN) ? g_deg[i] : 0;
    s[t] = v;
    __syncthreads();
    #pragma unroll
    for (int d = 1; d < 1024; d <<= 1) {
        int x = (t >= d) ? s[t - d] : 0;
        __syncthreads();
        s[t] += x;
        __syncthreads();
    }
    if (i < NN) g_off[i] = s[t] - v;          // exclusive within chunk
    if (t == 1023) g_part[blockIdx.x] = s[1023];
}

__global__ void k_scan2() {   // 1 block, 64 threads: scan the 49 chunk totals
    __shared__ int s[64];
    int t = threadIdx.x;
    const int nch = (NN + 1023) / 1024;
    int v = (t < nch) ? g_part[t] : 0;
    s[t] = v;
    __syncthreads();
    #pragma unroll
    for (int d = 1; d < 64; d <<= 1) {
        int x = (t >= d) ? s[t - d] : 0;
        __syncthreads();
        s[t] += x;
        __syncthreads();
    }
    if (t < nch) g_part[t] = s[t] - v;        // exclusive chunk bases
}

__global__ void k_scan3self() {
    int i = blockIdx.x * blockDim.x + threadIdx.x;
    if (i < NN) {
        int o = g_off[i] + g_part[i >> 10];
        g_off[i] = o;
        g_ssrc[o] = i;       // slot 0 of each segment = self loop
    }
    if (i == 0) g_off[NN] = ETOT;
}

// atomic-free scatter using precomputed ranks
__global__ void k_scatter(const int* __restrict__ ei) {
    int e4 = blockIdx.x * blockDim.x + threadIdx.x;
    if (e4 < EE / 4) {
        int4 s = ((const int4*)ei)[e4];
        int4 d = ((const int4*)(ei + EE))[e4];
        int4 r = ((const int4*)g_rank)[e4];
        g_ssrc[g_off[d.x] + r.x] = s.x;
        g_ssrc[g_off[d.y] + r.y] = s.y;
        g_ssrc[g_off[d.z] + r.z] = s.z;
        g_ssrc[g_off[d.w] + r.w] = s.w;
    }
}

// ---- GEMM1 (tensor cores): xp1 = x @ W1, fp16 in / fp32 acc ---------------
// block: 64 rows x 128 cols, 8 warps in 2(M) x 4(N); warp tile 32x32 = 2x2 wmma
// dynamic smem: Ah[64][136] half, Bh[128][136] half; C reuses the same buffer.
#define GA_LD 136
#define GA_ABYTES (64 * GA_LD * 2)
#define GA_BBYTES (128 * GA_LD * 2)
#define GA_SMEM   (GA_ABYTES + GA_BBYTES)
#define GC_LD 132

__global__ void __launch_bounds__(256)
k_gemm1(const float* __restrict__ x, const float* __restrict__ W,
        const float* __restrict__ asrc, const float* __restrict__ adst) {
    extern __shared__ char smem_raw[];
    __half* Ah = (__half*)smem_raw;
    __half* Bh = (__half*)(smem_raw + GA_ABYTES);
    float*  Cf = (float*)smem_raw;               // reused after mainloop

    int t = threadIdx.x;
    int lane = t & 31;
    int warp = t >> 5;
    int row0 = blockIdx.x * 64;
    int wm = warp >> 2;       // 0..1
    int wn = warp & 3;        // 0..3

    // load x tile (64x128 fp32 -> half)
    #pragma unroll
    for (int i = 0; i < 8; i++) {
        int idx = t + i * 256;           // 2048 float4
        int row = idx >> 5;
        int c4 = (idx & 31) * 4;
        int grow = row0 + row;
        float4 v = (grow < NN) ? *(const float4*)(x + grow * 128 + c4)
                               : make_float4(0, 0, 0, 0);
        __half* p = Ah + row * GA_LD + c4;
        p[0] = __float2half_rn(v.x); p[1] = __float2half_rn(v.y);
        p[2] = __float2half_rn(v.z); p[3] = __float2half_rn(v.w);
    }
    // load W (128x128 fp32 -> half), k-major rows
    #pragma unroll
    for (int i = 0; i < 16; i++) {
        int idx = t + i * 256;           // 4096 float4
        int row = idx >> 5;
        int c4 = (idx & 31) * 4;
        float4 v = *(const float4*)(W + row * 128 + c4);
        __half* p = Bh + row * GA_LD + c4;
        p[0] = __float2half_rn(v.x); p[1] = __float2half_rn(v.y);
        p[2] = __float2half_rn(v.z); p[3] = __float2half_rn(v.w);
    }
    __syncthreads();

    wmma::fragment<wmma::accumulator, 16, 16, 16, float> c[2][2];
    #pragma unroll
    for (int i = 0; i < 2; i++)
        #pragma unroll
        for (int j = 0; j < 2; j++)
            wmma::fill_fragment(c[i][j], 0.0f);

    #pragma unroll
    for (int k0 = 0; k0 < 128; k0 += 16) {
        wmma::fragment<wmma::matrix_a, 16, 16, 16, __half, wmma::row_major> a[2];
        wmma::fragment<wmma::matrix_b, 16, 16, 16, __half, wmma::row_major> b[2];
        #pragma unroll
        for (int i = 0; i < 2; i++)
            wmma::load_matrix_sync(a[i], Ah + (wm * 32 + i * 16) * GA_LD + k0, GA_LD);
        #pragma unroll
        for (int j = 0; j < 2; j++)
            wmma::load_matrix_sync(b[j], Bh + k0 * GA_LD + wn * 32 + j * 16, GA_LD);
        #pragma unroll
        for (int i = 0; i < 2; i++)
            #pragma unroll
            for (int j = 0; j < 2; j++)
                wmma::mma_sync(c[i][j], a[i], b[j], c[i][j]);
    }
    __syncthreads();   // done reading Ah/Bh before overwriting with Cf

    #pragma unroll
    for (int i = 0; i < 2; i++)
        #pragma unroll
        for (int j = 0; j < 2; j++)
            wmma::store_matrix_sync(Cf + (wm * 32 + i * 16) * GC_LD + wn * 32 + j * 16,
                                    c[i][j], GC_LD, wmma::mem_row_major);
    __syncthreads();

    // epilogue: fp16 store + fused per-head attention dots
    int c0 = lane * 4;
    float4 asv = *(const float4*)(asrc + c0);
    float4 adv = *(const float4*)(adst + c0);
    int h = lane >> 3;
    #pragma unroll
    for (int rr = 0; rr < 8; rr++) {
        int row = warp * 8 + rr;
        int grow = row0 + row;
        float4 v = *(const float4*)(Cf + row * GC_LD + c0);
        if (grow < NN) {
            __half2 h0 = __floats2half2_rn(v.x, v.y);
            __half2 h1 = __floats2half2_rn(v.z, v.w);
            uint2 pk;
            pk.x = *(unsigned*)&h0;
            pk.y = *(unsigned*)&h1;
            *(uint2*)(g_xp1h + grow * 64 + lane * 2) = pk;
        }
        float ps = v.x * asv.x + v.y * asv.y + v.z * asv.z + v.w * asv.w;
        float pd = v.x * adv.x + v.y * adv.y + v.z * adv.z + v.w * adv.w;
        #pragma unroll
        for (int o = 1; o < 8; o <<= 1) {
            ps += __shfl_xor_sync(0xffffffffu, ps, o);
            pd += __shfl_xor_sync(0xffffffffu, pd, o);
        }
        if ((lane & 7) == 0 && grow < NN) {
            g_as1[grow * 4 + h] = ps;
            g_ad1[grow * 4 + h] = pd;
        }
    }
}

// ---- layer-1 aggregation: warp per node, fp16 gather, no max pass ----------
__global__ void __launch_bounds__(256) k_agg1(const float* __restrict__ b1) {
    int gw = (blockIdx.x * blockDim.x + threadIdx.x) >> 5;
    int lane = threadIdx.x & 31;
    if (gw >= NN) return;
    int i = gw;
    int s0 = g_off[i], s1 = g_off[i + 1];
    int h = lane >> 3;
    int es = lane & 7;
    float adh = g_ad1[i * 4 + h];

    float den = 0.f;
    float ax = 0.f, ay = 0.f, az = 0.f, aw = 0.f;
    int base = s0;
    for (; base + 8 <= s1; base += 8) {
        int src_l = g_ssrc[base + es];
        float w_l = __expf(leaky(g_as1[src_l * 4 + h] + adh));
        den += w_l;
        #pragma unroll 8
        for (int j = 0; j < 8; j++) {
            int sl = (h << 3) | j;
            int src = __shfl_sync(0xffffffffu, src_l, sl);
            float w  = __shfl_sync(0xffffffffu, w_l, sl);
            uint2 p = *(const uint2*)(g_xp1h + src * 64 + lane * 2);
            float2 v0 = __half22float2(*(__half2*)&p.x);
            float2 v1 = __half22float2(*(__half2*)&p.y);
            ax = fmaf(w, v0.x, ax); ay = fmaf(w, v0.y, ay);
            az = fmaf(w, v1.x, az); aw = fmaf(w, v1.y, aw);
        }
    }
    if (base < s1) {
        int e = base + es;
        int src_l = 0;
        float w_l = 0.f;
        if (e < s1) {
            src_l = g_ssrc[e];
            w_l = __expf(leaky(g_as1[src_l * 4 + h] + adh));
        }
        den += w_l;
        int n = s1 - base;
        for (int j = 0; j < n; j++) {
            int sl = (h << 3) | j;
            int src = __shfl_sync(0xffffffffu, src_l, sl);
            float w  = __shfl_sync(0xffffffffu, w_l, sl);
            uint2 p = *(const uint2*)(g_xp1h + src * 64 + lane * 2);
            float2 v0 = __half22float2(*(__half2*)&p.x);
            float2 v1 = __half22float2(*(__half2*)&p.y);
            ax = fmaf(w, v0.x, ax); ay = fmaf(w, v0.y, ay);
            az = fmaf(w, v1.x, az); aw = fmaf(w, v1.y, aw);
        }
    }
    den += __shfl_xor_sync(0xffffffffu, den, 1);
    den += __shfl_xor_sync(0xffffffffu, den, 2);
    den += __shfl_xor_sync(0xffffffffu, den, 4);
    float inv = 1.0f / den;
    float4 bb = *(const float4*)(b1 + lane * 4);
    float4 o;
    o.x = fmaxf(fmaf(ax, inv, bb.x), 0.f);
    o.y = fmaxf(fmaf(ay, inv, bb.y), 0.f);
    o.z = fmaxf(fmaf(az, inv, bb.z), 0.f);
    o.w = fmaxf(fmaf(aw, inv, bb.w), 0.f);
    *(float4*)(g_h + i * 128 + lane * 4) = o;
}

// ---- GEMM2: xp2 = h @ W2 (50000x128 @ 128x32) + fused attention dots -------
__global__ void __launch_bounds__(256)
k_gemm2(const float* __restrict__ W2,
        const float* __restrict__ asrc, const float* __restrict__ adst) {
    __shared__ float Ws[32][32];    // k-major
    __shared__ float Xs[32][128];   // k-major
    int t = threadIdx.x;
    int lane = t & 31;
    int row0 = blockIdx.x * 128;
    int c0 = (t & 15) * 2;
    int r0 = (t >> 4) * 8;

    unsigned long long acc[8];
    #pragma unroll
    for (int r = 0; r < 8; r++) acc[r] = 0ull;

    for (int kc = 0; kc < 128; kc += 32) {
        ((float4*)&Ws[0][0])[t] = ((const float4*)(W2 + kc * 32))[t];
        #pragma unroll
        for (int i = 0; i < 4; i++) {
            int id = t + i * 256;          // 1024 float4 = 128 rows x 32 k
            int row = id >> 3;
            int k4 = (id & 7) * 4;
            int grow = row0 + row;
            float4 v = (grow < NN) ? *(const float4*)(g_h + grow * 128 + kc + k4)
                                   : make_float4(0, 0, 0, 0);
            Xs[k4 + 0][row] = v.x; Xs[k4 + 1][row] = v.y;
            Xs[k4 + 2][row] = v.z; Xs[k4 + 3][row] = v.w;
        }
        __syncthreads();
        #pragma unroll 8
        for (int k = 0; k < 32; k++) {
            float4 alo = *(const float4*)&Xs[k][r0];
            float4 ahi = *(const float4*)&Xs[k][r0 + 4];
            unsigned long long b = *(const unsigned long long*)&Ws[k][c0];
            unsigned long long ap;
            ap = pack2(alo.x); fma2(acc[0], ap, b);
            ap = pack2(alo.y); fma2(acc[1], ap, b);
            ap = pack2(alo.z); fma2(acc[2], ap, b);
            ap = pack2(alo.w); fma2(acc[3], ap, b);
            ap = pack2(ahi.x); fma2(acc[4], ap, b);
            ap = pack2(ahi.y); fma2(acc[5], ap, b);
            ap = pack2(ahi.z); fma2(acc[6], ap, b);
            ap = pack2(ahi.w); fma2(acc[7], ap, b);
        }
        __syncthreads();
    }

    float2 asv = *(const float2*)(asrc + c0);
    float2 adv = *(const float2*)(adst + c0);
    #pragma unroll
    for (int r = 0; r < 8; r++) {
        float2 v = unpk2(acc[r]);
        int grow = row0 + r0 + r;
        if (grow < NN) {
            __half2 hv = __floats2half2_rn(v.x, v.y);
            *(__half2*)(g_xp2h + grow * 32 + c0) = hv;
        }
        float ps = v.x * asv.x + v.y * asv.y;
        float pd = v.x * adv.x + v.y * adv.y;
        #pragma unroll
        for (int o = 1; o < 16; o <<= 1) {
            ps += __shfl_xor_sync(0xffffffffu, ps, o);
            pd += __shfl_xor_sync(0xffffffffu, pd, o);
        }
        if ((lane & 15) == 0 && grow < NN) {
            g_as2[grow] = ps;
            g_ad2[grow] = pd;
        }
    }
}

// ---- layer-2 aggregation: warp per node, fp16 gather, no max pass ----------
__global__ void __launch_bounds__(256)
k_agg2(const float* __restrict__ b2, float* __restrict__ out) {
    int gw = (blockIdx.x * blockDim.x + threadIdx.x) >> 5;
    int lane = threadIdx.x & 31;
    if (gw >= NN) return;
    int i = gw;
    int s0 = g_off[i], s1 = g_off[i + 1];
    float ad = g_ad2[i];

    float den = 0.f, acc = 0.f;
    for (int base = s0; base < s1; base += 32) {
        int e = base + lane;
        int src_l = 0;
        float w_l = 0.f;
        if (e < s1) {
            src_l = g_ssrc[e];
            w_l = __expf(leaky(g_as2[src_l] + ad));
        }
        den += w_l;
        int n = min(32, s1 - base);
        #pragma unroll 4
        for (int j = 0; j < n; j++) {
            int src = __shfl_sync(0xffffffffu, src_l, j);
            float w  = __shfl_sync(0xffffffffu, w_l, j);
            float v = __half2float(g_xp2h[src * 32 + lane]);
            acc = fmaf(w, v, acc);
        }
    }
    #pragma unroll
    for (int o = 16; o; o >>= 1)
        den += __shfl_xor_sync(0xffffffffu, den, o);
    out[i * 32 + lane] = acc / den + b2[lane];
}

// ---------------- launch ----------------------------------------------------
extern "C" void kernel_launch(void* const* d_in, const int* in_sizes, int n_in,
                              void* d_out, int out_size) {
    const float* x   = (const float*)d_in[0];
    const int*   ei  = (const int*)  d_in[1];
    const float* W1  = (const float*)d_in[2];
    const float* as1 = (const float*)d_in[3];
    const float* ad1 = (const float*)d_in[4];
    const float* b1  = (const float*)d_in[5];
    const float* W2  = (const float*)d_in[6];
    const float* as2 = (const float*)d_in[7];
    const float* ad2 = (const float*)d_in[8];
    const float* b2  = (const float*)d_in[9];
    float* out = (float*)d_out;

    const int nblkN = (NN + 255) / 256;
    const int nchunks = (NN + 1023) / 1024;
    const int nblkE4 = (EE / 4 + 255) / 256;
    const int nblkW = (NN * 32 + 255) / 256;   // one warp per node

    static bool attr_set = false;
    if (!attr_set) {
        cudaFuncSetAttribute(k_gemm1, cudaFuncAttributeMaxDynamicSharedMemorySize,
                             GA_SMEM);
        attr_set = true;
    }

    // CSR build (6 launches)
    k_init<<<nblkN, 256>>>();
    k_rank<<<nblkE4, 256>>>(ei + EE);
    k_scan1<<<nchunks, 1024>>>();
    k_scan2<<<1, 64>>>();
    k_scan3self<<<nblkN, 256>>>();
    k_scatter<<<nblkE4, 256>>>(ei);

    // layer 1
    k_gemm1<<<(NN + 63) / 64, 256, GA_SMEM>>>(x, W1, as1, ad1);
    k_agg1<<<nblkW, 256>>>(b1);

    // layer 2
    k_gemm2<<<(NN + 127) / 128, 256>>>(W2, as2, ad2);
    k_agg2<<<nblkW, 256>>>(b2, out);
}

// round 5
// speedup vs baseline: 1.5848x; 1.1216x over previous
#include <cuda_runtime.h>
#include <cuda_fp16.h>
#include <mma.h>

using namespace nvcuda;

// Problem constants (fixed by the dataset)
#define NN   50000
#define EE   800000
#define ETOT (NN + EE)      // edges + self loops
#define D1   128            // DIN and H*C1
#define HH   4
#define CC1  32
#define DOUT 32
#define SLOPE 0.2f
#define NCH  ((NN + 1023) / 1024)   // 49 scan chunks

// ---------------- scratch (static device arrays: no allocation) -------------
__device__ int     g_deg[NN];        // zero at load; re-zeroed by k_scan1 each run
__device__ int     g_off[NN + 1];
__device__ int     g_rank[EE];
__device__ int     g_part[64];
__device__ int     g_ssrc[ETOT];
__device__ __half2 g_xp1h[NN * 64];  // xp1 in fp16, 2 ch per half2
__device__ __half  g_hh[NN * D1];    // hidden h in fp16
__device__ __half  g_xp2h[NN * DOUT];
__device__ float   g_as1[NN * HH];
__device__ float   g_ad1[NN * HH];
__device__ float   g_as2[NN];
__device__ float   g_ad2[NN];

__device__ __forceinline__ float leaky(float v) { return v > 0.f ? v : SLOPE * v; }

// ---------------- CSR build -------------------------------------------------
// degree count + per-edge rank in one pass (g_deg starts at 0 every run)
__global__ void k_rank(const int* __restrict__ dst) {
    int e4 = blockIdx.x * blockDim.x + threadIdx.x;
    if (e4 < EE / 4) {
        int4 d = ((const int4*)dst)[e4];
        int4 r;
        r.x = atomicAdd(&g_deg[d.x], 1);
        r.y = atomicAdd(&g_deg[d.y], 1);
        r.z = atomicAdd(&g_deg[d.z], 1);
        r.w = atomicAdd(&g_deg[d.w], 1);
        ((int4*)g_rank)[e4] = r;
    }
}

__global__ void __launch_bounds__(1024) k_scan1() {  // grid = NCH
    __shared__ int s[1024];
    int t = threadIdx.x;
    int i = blockIdx.x * 1024 + t;
    int v = 0;
    if (i < NN) {
        v = g_deg[i] + 1;    // +1 = self loop
        g_deg[i] = 0;        // reset for the next replay (deterministic)
    }
    s[t] = v;
    __syncthreads();
    #pragma unroll
    for (int d = 1; d < 1024; d <<= 1) {
        int x = (t >= d) ? s[t - d] : 0;
        __syncthreads();
        s[t] += x;
        __syncthreads();
    }
    if (i < NN) g_off[i] = s[t] - v;          // exclusive within chunk
    if (t == 1023) g_part[blockIdx.x] = s[1023];
}

// fused: scan the 49 chunk totals (redundantly per block) + finalize offsets
// + plant self loops
__global__ void k_scan23self() {
    __shared__ int sb[64];
    int t = threadIdx.x;
    int v0 = 0;
    if (t < 64) {
        v0 = (t < NCH) ? g_part[t] : 0;
        sb[t] = v0;
    }
    __syncthreads();
    #pragma unroll
    for (int d = 1; d < 64; d <<= 1) {
        int x = 0;
        if (t < 64 && t >= d) x = sb[t - d];
        __syncthreads();
        if (t < 64) sb[t] += x;
        __syncthreads();
    }
    if (t < 64) sb[t] -= v0;   // exclusive chunk bases
    __syncthreads();

    int i = blockIdx.x * blockDim.x + t;
    if (i < NN) {
        int o = g_off[i] + sb[i >> 10];
        g_off[i] = o;
        g_ssrc[o] = i;          // slot 0 of each segment = self loop
    }
    if (i == 0) g_off[NN] = ETOT;
}

// atomic-free scatter using precomputed ranks (rank 0-based; +1 skips self slot)
__global__ void k_scatter(const int* __restrict__ ei) {
    int e4 = blockIdx.x * blockDim.x + threadIdx.x;
    if (e4 < EE / 4) {
        int4 s = ((const int4*)ei)[e4];
        int4 d = ((const int4*)(ei + EE))[e4];
        int4 r = ((const int4*)g_rank)[e4];
        g_ssrc[g_off[d.x] + 1 + r.x] = s.x;
        g_ssrc[g_off[d.y] + 1 + r.y] = s.y;
        g_ssrc[g_off[d.z] + 1 + r.z] = s.z;
        g_ssrc[g_off[d.w] + 1 + r.w] = s.w;
    }
}

// ---- GEMM1 (tensor cores): xp1 = x @ W1, fp16 in / fp32 acc ---------------
#define GA_LD 136
#define GA_ABYTES (64 * GA_LD * 2)
#define GA_BBYTES (128 * GA_LD * 2)
#define GA_SMEM   (GA_ABYTES + GA_BBYTES)
#define GC_LD 132

__global__ void __launch_bounds__(256)
k_gemm1(const float* __restrict__ x, const float* __restrict__ W,
        const float* __restrict__ asrc, const float* __restrict__ adst) {
    extern __shared__ char smem_raw[];
    __half* Ah = (__half*)smem_raw;
    __half* Bh = (__half*)(smem_raw + GA_ABYTES);
    float*  Cf = (float*)smem_raw;               // reused after mainloop

    int t = threadIdx.x;
    int lane = t & 31;
    int warp = t >> 5;
    int row0 = blockIdx.x * 64;
    int wm = warp >> 2;       // 0..1
    int wn = warp & 3;        // 0..3

    // load x tile (64x128 fp32 -> half)
    #pragma unroll
    for (int i = 0; i < 8; i++) {
        int idx = t + i * 256;           // 2048 float4
        int row = idx >> 5;
        int c4 = (idx & 31) * 4;
        int grow = row0 + row;
        float4 v = (grow < NN) ? *(const float4*)(x + grow * 128 + c4)
                               : make_float4(0, 0, 0, 0);
        __half* p = Ah + row * GA_LD + c4;
        p[0] = __float2half_rn(v.x); p[1] = __float2half_rn(v.y);
        p[2] = __float2half_rn(v.z); p[3] = __float2half_rn(v.w);
    }
    // load W (128x128 fp32 -> half), k-major rows
    #pragma unroll
    for (int i = 0; i < 16; i++) {
        int idx = t + i * 256;           // 4096 float4
        int row = idx >> 5;
        int c4 = (idx & 31) * 4;
        float4 v = *(const float4*)(W + row * 128 + c4);
        __half* p = Bh + row * GA_LD + c4;
        p[0] = __float2half_rn(v.x); p[1] = __float2half_rn(v.y);
        p[2] = __float2half_rn(v.z); p[3] = __float2half_rn(v.w);
    }
    __syncthreads();

    wmma::fragment<wmma::accumulator, 16, 16, 16, float> c[2][2];
    #pragma unroll
    for (int i = 0; i < 2; i++)
        #pragma unroll
        for (int j = 0; j < 2; j++)
            wmma::fill_fragment(c[i][j], 0.0f);

    #pragma unroll
    for (int k0 = 0; k0 < 128; k0 += 16) {
        wmma::fragment<wmma::matrix_a, 16, 16, 16, __half, wmma::row_major> a[2];
        wmma::fragment<wmma::matrix_b, 16, 16, 16, __half, wmma::row_major> b[2];
        #pragma unroll
        for (int i = 0; i < 2; i++)
            wmma::load_matrix_sync(a[i], Ah + (wm * 32 + i * 16) * GA_LD + k0, GA_LD);
        #pragma unroll
        for (int j = 0; j < 2; j++)
            wmma::load_matrix_sync(b[j], Bh + k0 * GA_LD + wn * 32 + j * 16, GA_LD);
        #pragma unroll
        for (int i = 0; i < 2; i++)
            #pragma unroll
            for (int j = 0; j < 2; j++)
                wmma::mma_sync(c[i][j], a[i], b[j], c[i][j]);
    }
    __syncthreads();   // done reading Ah/Bh before overwriting with Cf

    #pragma unroll
    for (int i = 0; i < 2; i++)
        #pragma unroll
        for (int j = 0; j < 2; j++)
            wmma::store_matrix_sync(Cf + (wm * 32 + i * 16) * GC_LD + wn * 32 + j * 16,
                                    c[i][j], GC_LD, wmma::mem_row_major);
    __syncthreads();

    // epilogue: fp16 store + fused per-head attention dots
    int c0 = lane * 4;
    float4 asv = *(const float4*)(asrc + c0);
    float4 adv = *(const float4*)(adst + c0);
    int h = lane >> 3;
    #pragma unroll
    for (int rr = 0; rr < 8; rr++) {
        int row = warp * 8 + rr;
        int grow = row0 + row;
        float4 v = *(const float4*)(Cf + row * GC_LD + c0);
        if (grow < NN) {
            __half2 h0 = __floats2half2_rn(v.x, v.y);
            __half2 h1 = __floats2half2_rn(v.z, v.w);
            uint2 pk;
            pk.x = *(unsigned*)&h0;
            pk.y = *(unsigned*)&h1;
            *(uint2*)(g_xp1h + grow * 64 + lane * 2) = pk;
        }
        float ps = v.x * asv.x + v.y * asv.y + v.z * asv.z + v.w * asv.w;
        float pd = v.x * adv.x + v.y * adv.y + v.z * adv.z + v.w * adv.w;
        #pragma unroll
        for (int o = 1; o < 8; o <<= 1) {
            ps += __shfl_xor_sync(0xffffffffu, ps, o);
            pd += __shfl_xor_sync(0xffffffffu, pd, o);
        }
        if ((lane & 7) == 0 && grow < NN) {
            g_as1[grow * 4 + h] = ps;
            g_ad1[grow * 4 + h] = pd;
        }
    }
}

// ---- layer-1 aggregation: warp per node, fp16 gather, no max pass ----------
__global__ void __launch_bounds__(256) k_agg1(const float* __restrict__ b1) {
    int gw = (blockIdx.x * blockDim.x + threadIdx.x) >> 5;
    int lane = threadIdx.x & 31;
    if (gw >= NN) return;
    int i = gw;
    int s0 = g_off[i], s1 = g_off[i + 1];
    int h = lane >> 3;
    int es = lane & 7;
    float adh = g_ad1[i * 4 + h];

    float den = 0.f;
    float ax = 0.f, ay = 0.f, az = 0.f, aw = 0.f;
    int base = s0;
    for (; base + 8 <= s1; base += 8) {
        int src_l = g_ssrc[base + es];
        float w_l = __expf(leaky(g_as1[src_l * 4 + h] + adh));
        den += w_l;
        #pragma unroll 8
        for (int j = 0; j < 8; j++) {
            int sl = (h << 3) | j;
            int src = __shfl_sync(0xffffffffu, src_l, sl);
            float w  = __shfl_sync(0xffffffffu, w_l, sl);
            uint2 p = *(const uint2*)(g_xp1h + src * 64 + lane * 2);
            float2 v0 = __half22float2(*(__half2*)&p.x);
            float2 v1 = __half22float2(*(__half2*)&p.y);
            ax = fmaf(w, v0.x, ax); ay = fmaf(w, v0.y, ay);
            az = fmaf(w, v1.x, az); aw = fmaf(w, v1.y, aw);
        }
    }
    if (base < s1) {
        int e = base + es;
        int src_l = 0;
        float w_l = 0.f;
        if (e < s1) {
            src_l = g_ssrc[e];
            w_l = __expf(leaky(g_as1[src_l * 4 + h] + adh));
        }
        den += w_l;
        int n = s1 - base;
        for (int j = 0; j < n; j++) {
            int sl = (h << 3) | j;
            int src = __shfl_sync(0xffffffffu, src_l, sl);
            float w  = __shfl_sync(0xffffffffu, w_l, sl);
            uint2 p = *(const uint2*)(g_xp1h + src * 64 + lane * 2);
            float2 v0 = __half22float2(*(__half2*)&p.x);
            float2 v1 = __half22float2(*(__half2*)&p.y);
            ax = fmaf(w, v0.x, ax); ay = fmaf(w, v0.y, ay);
            az = fmaf(w, v1.x, az); aw = fmaf(w, v1.y, aw);
        }
    }
    den += __shfl_xor_sync(0xffffffffu, den, 1);
    den += __shfl_xor_sync(0xffffffffu, den, 2);
    den += __shfl_xor_sync(0xffffffffu, den, 4);
    float inv = 1.0f / den;
    float4 bb = *(const float4*)(b1 + lane * 4);
    float ox = fmaxf(fmaf(ax, inv, bb.x), 0.f);
    float oy = fmaxf(fmaf(ay, inv, bb.y), 0.f);
    float oz = fmaxf(fmaf(az, inv, bb.z), 0.f);
    float ow = fmaxf(fmaf(aw, inv, bb.w), 0.f);
    __half2 h0 = __floats2half2_rn(ox, oy);
    __half2 h1 = __floats2half2_rn(oz, ow);
    uint2 pk;
    pk.x = *(unsigned*)&h0;
    pk.y = *(unsigned*)&h1;
    *(uint2*)(g_hh + i * 128 + lane * 4) = pk;
}

// ---- GEMM2 (tensor cores): xp2 = h @ W2 (50000x128 @ 128x32) + att dots ----
// block: 128 rows x 32 cols, 8 warps, each warp 16 rows (2 wmma frags over N)
#define G2_ALD 136
#define G2_BLD 40
#define G2_CLD 36

__global__ void __launch_bounds__(256)
k_gemm2(const float* __restrict__ W2,
        const float* __restrict__ asrc, const float* __restrict__ adst) {
    __shared__ __half Ah[128 * G2_ALD];    // 34816 B
    __shared__ __half Bh[128 * G2_BLD];    // 10240 B
    float* Cf = (float*)Ah;                // reused after mainloop (18432 B)

    int t = threadIdx.x;
    int warp = t >> 5;
    int row0 = blockIdx.x * 128;

    // load h tile (128x128 half, straight copy, 16B chunks)
    #pragma unroll
    for (int i = 0; i < 8; i++) {
        int idx = t + i * 256;          // 2048 uint4
        int row = idx >> 4;
        int q = idx & 15;               // 8 half per uint4
        int grow = row0 + row;
        uint4 v = (grow < NN) ? *(const uint4*)(g_hh + grow * 128 + q * 8)
                              : make_uint4(0, 0, 0, 0);
        *(uint4*)(Ah + row * G2_ALD + q * 8) = v;
    }
    // load W2 (128x32 fp32 -> half)
    #pragma unroll
    for (int i = 0; i < 4; i++) {
        int idx = t + i * 256;          // 1024 float4
        int row = idx >> 3;
        int c4 = (idx & 7) * 4;
        float4 v = *(const float4*)(W2 + row * 32 + c4);
        __half* p = Bh + row * G2_BLD + c4;
        p[0] = __float2half_rn(v.x); p[1] = __float2half_rn(v.y);
        p[2] = __float2half_rn(v.z); p[3] = __float2half_rn(v.w);
    }
    __syncthreads();

    wmma::fragment<wmma::accumulator, 16, 16, 16, float> c[2];
    wmma::fill_fragment(c[0], 0.0f);
    wmma::fill_fragment(c[1], 0.0f);

    #pragma unroll
    for (int k0 = 0; k0 < 128; k0 += 16) {
        wmma::fragment<wmma::matrix_a, 16, 16, 16, __half, wmma::row_major> a;
        wmma::fragment<wmma::matrix_b, 16, 16, 16, __half, wmma::row_major> b[2];
        wmma::load_matrix_sync(a, Ah + (warp * 16) * G2_ALD + k0, G2_ALD);
        wmma::load_matrix_sync(b[0], Bh + k0 * G2_BLD + 0, G2_BLD);
        wmma::load_matrix_sync(b[1], Bh + k0 * G2_BLD + 16, G2_BLD);
        wmma::mma_sync(c[0], a, b[0], c[0]);
        wmma::mma_sync(c[1], a, b[1], c[1]);
    }
    __syncthreads();

    wmma::store_matrix_sync(Cf + (warp * 16) * G2_CLD + 0,  c[0], G2_CLD,
                            wmma::mem_row_major);
    wmma::store_matrix_sync(Cf + (warp * 16) * G2_CLD + 16, c[1], G2_CLD,
                            wmma::mem_row_major);
    __syncthreads();

    // epilogue: 2 threads per row, 16 cols each
    int row = t >> 1;
    int c0 = (t & 1) * 16;
    int grow = row0 + row;
    float v[16];
    #pragma unroll
    for (int j = 0; j < 16; j++) v[j] = Cf[row * G2_CLD + c0 + j];

    float ps = 0.f, pd = 0.f;
    #pragma unroll
    for (int j = 0; j < 16; j++) {
        ps = fmaf(v[j], asrc[c0 + j], ps);
        pd = fmaf(v[j], adst[c0 + j], pd);
    }
    ps += __shfl_xor_sync(0xffffffffu, ps, 1);
    pd += __shfl_xor_sync(0xffffffffu, pd, 1);

    if (grow < NN) {
        __half hv[16];
        #pragma unroll
        for (int j = 0; j < 16; j++) hv[j] = __float2half_rn(v[j]);
        *(uint4*)(g_xp2h + grow * 32 + c0)     = *(uint4*)&hv[0];
        *(uint4*)(g_xp2h + grow * 32 + c0 + 8) = *(uint4*)&hv[8];
        if ((t & 1) == 0) {
            g_as2[grow] = ps;
            g_ad2[grow] = pd;
        }
    }
}

// ---- layer-2 aggregation: warp per node, fp16 gather, no max pass ----------
__global__ void __launch_bounds__(256)
k_agg2(const float* __restrict__ b2, float* __restrict__ out) {
    int gw = (blockIdx.x * blockDim.x + threadIdx.x) >> 5;
    int lane = threadIdx.x & 31;
    if (gw >= NN) return;
    int i = gw;
    int s0 = g_off[i], s1 = g_off[i + 1];
    float ad = g_ad2[i];

    float den = 0.f, acc = 0.f;
    for (int base = s0; base < s1; base += 32) {
        int e = base + lane;
        int src_l = 0;
        float w_l = 0.f;
        if (e < s1) {
            src_l = g_ssrc[e];
            w_l = __expf(leaky(g_as2[src_l] + ad));
        }
        den += w_l;
        int n = min(32, s1 - base);
        #pragma unroll 4
        for (int j = 0; j < n; j++) {
            int src = __shfl_sync(0xffffffffu, src_l, j);
            float w  = __shfl_sync(0xffffffffu, w_l, j);
            float v = __half2float(g_xp2h[src * 32 + lane]);
            acc = fmaf(w, v, acc);
        }
    }
    #pragma unroll
    for (int o = 16; o; o >>= 1)
        den += __shfl_xor_sync(0xffffffffu, den, o);
    out[i * 32 + lane] = acc / den + b2[lane];
}

// ---------------- launch ----------------------------------------------------
extern "C" void kernel_launch(void* const* d_in, const int* in_sizes, int n_in,
                              void* d_out, int out_size) {
    const float* x   = (const float*)d_in[0];
    const int*   ei  = (const int*)  d_in[1];
    const float* W1  = (const float*)d_in[2];
    const float* as1 = (const float*)d_in[3];
    const float* ad1 = (const float*)d_in[4];
    const float* b1  = (const float*)d_in[5];
    const float* W2  = (const float*)d_in[6];
    const float* as2 = (const float*)d_in[7];
    const float* ad2 = (const float*)d_in[8];
    const float* b2  = (const float*)d_in[9];
    float* out = (float*)d_out;

    const int nblkN  = (NN + 255) / 256;
    const int nblkE4 = (EE / 4 + 255) / 256;
    const int nblkW  = (NN * 32 + 255) / 256;   // one warp per node

    static bool init_done = false;
    static cudaStream_t s2 = 0;
    static cudaEvent_t evF = 0, evJ = 0;
    if (!init_done) {
        cudaFuncSetAttribute(k_gemm1, cudaFuncAttributeMaxDynamicSharedMemorySize,
                             GA_SMEM);
        cudaStream_t st;
        if (cudaStreamCreateWithFlags(&st, cudaStreamNonBlocking) == cudaSuccess &&
            cudaEventCreateWithFlags(&evF, cudaEventDisableTiming) == cudaSuccess &&
            cudaEventCreateWithFlags(&evJ, cudaEventDisableTiming) == cudaSuccess) {
            s2 = st;
        } else {
            s2 = 0;
        }
        init_done = true;
    }

    // fork GEMM1 (independent of CSR build) onto second stream
    if (s2) {
        cudaEventRecord(evF, 0);
        cudaStreamWaitEvent(s2, evF, 0);
        k_gemm1<<<(NN + 63) / 64, 256, GA_SMEM, s2>>>(x, W1, as1, ad1);
        cudaEventRecord(evJ, s2);
    }

    // CSR build on stream 0 (4 launches)
    k_rank<<<nblkE4, 256>>>(ei + EE);
    k_scan1<<<NCH, 1024>>>();
    k_scan23self<<<nblkN, 256>>>();
    k_scatter<<<nblkE4, 256>>>(ei);

    if (s2) {
        cudaStreamWaitEvent(0, evJ, 0);
    } else {
        k_gemm1<<<(NN + 63) / 64, 256, GA_SMEM>>>(x, W1, as1, ad1);
    }

    // layer 1 aggregation, layer 2
    k_agg1<<<nblkW, 256>>>(b1);
    k_gemm2<<<(NN + 127) / 128, 256>>>(W2, as2, ad2);
    k_agg2<<<nblkW, 256>>>(b2, out);
}